// round 2
// baseline (speedup 1.0000x reference)
#include <cuda_runtime.h>
#include <math.h>

#define HDIM 128
#define TILE_M 128
#define XS 132          // x / h smem row stride (A-frag conflict-free)
#define WSS 136         // weight smem row stride (B-frag conflict-free)
#define NRE 8
#define NSE 2
#define NEXP 10

// SMEM layout (floats)
#define SM_XS 0                      // 128*132 = 16896
#define SM_WS 16896                  // 128*136 = 17408
#define SM_HS 34304                  // 128*132 = 16896
#define SM_MG 51200                  // 128*8   = 1024
#define SM_B1 52224                  // 128
#define SM_B2 52352                  // 10*128  = 1280
#define SM_FLOATS 53632              // 214528 bytes

__device__ __forceinline__ unsigned f2tf(float x) {
    unsigned u;
    asm("cvt.rna.tf32.f32 %0, %1;" : "=r"(u) : "f"(x));
    return u;
}

__device__ __forceinline__ void mma_tf32(float d[4], const unsigned a[4], const unsigned b[2]) {
    asm volatile(
        "mma.sync.aligned.m16n8k8.row.col.f32.tf32.tf32.f32 "
        "{%0,%1,%2,%3}, {%4,%5,%6,%7}, {%8,%9}, {%0,%1,%2,%3};"
        : "+f"(d[0]), "+f"(d[1]), "+f"(d[2]), "+f"(d[3])
        : "r"(a[0]), "r"(a[1]), "r"(a[2]), "r"(a[3]), "r"(b[0]), "r"(b[1]));
}

__device__ __forceinline__ float gelu_tanh(float x) {
    float x3 = x * x * x;
    float inner = 0.7978845608028654f * (x + 0.044715f * x3);
    return 0.5f * x * (1.0f + tanhf(inner));
}

// 128x128x128 warp-tiled tf32 GEMM: acc[2][8][4] += A[128,128] * B[128,128]
// A rows [mrow, mrow+32), B cols [ncol, ncol+64) for this warp.
__device__ __forceinline__ void gemm128(const float* __restrict__ A, const float* __restrict__ B,
                                        int mrow, int ncol, int g, int c, float acc[2][8][4]) {
#pragma unroll 4
    for (int k0 = 0; k0 < 16; k0++) {
        const int kb = k0 * 8;
        unsigned a[2][4];
#pragma unroll
        for (int i = 0; i < 2; i++) {
            const float* ap = A + (mrow + i * 16 + g) * XS + kb + c;
            a[i][0] = __float_as_uint(ap[0]);
            a[i][1] = __float_as_uint(ap[8 * XS]);
            a[i][2] = __float_as_uint(ap[4]);
            a[i][3] = __float_as_uint(ap[8 * XS + 4]);
        }
#pragma unroll
        for (int j = 0; j < 8; j++) {
            unsigned b[2];
            const float* bp = B + (kb + c) * WSS + ncol + j * 8 + g;
            b[0] = __float_as_uint(bp[0]);
            b[1] = __float_as_uint(bp[4 * WSS]);
            mma_tf32(acc[0][j], a[0], b);
            mma_tf32(acc[1][j], a[1], b);
        }
    }
}

__device__ __forceinline__ void load_w_tf32(const float* __restrict__ W, float* __restrict__ wsm, int tid) {
#pragma unroll
    for (int i = 0; i < 16; i++) {
        int idx = tid + i * 256;
        int k = idx >> 5;
        int c4 = (idx & 31) << 2;
        float4 v = *reinterpret_cast<const float4*>(W + k * HDIM + c4);
        v.x = __uint_as_float(f2tf(v.x));
        v.y = __uint_as_float(f2tf(v.y));
        v.z = __uint_as_float(f2tf(v.z));
        v.w = __uint_as_float(f2tf(v.w));
        *reinterpret_cast<float4*>(wsm + k * WSS + c4) = v;
    }
}

__global__ void __launch_bounds__(256, 1)
moe_fused_kernel(const float* __restrict__ x,
                 const float* __restrict__ Wr1, const float* __restrict__ br1,
                 const float* __restrict__ Wr2, const float* __restrict__ br2,
                 const float* __restrict__ We1, const float* __restrict__ be1,
                 const float* __restrict__ We2, const float* __restrict__ be2,
                 const float* __restrict__ Ws1, const float* __restrict__ bs1,
                 const float* __restrict__ Ws2, const float* __restrict__ bs2,
                 float* __restrict__ out) {
    extern __shared__ float smf[];
    float* xs  = smf + SM_XS;
    float* wsm = smf + SM_WS;
    float* hs  = smf + SM_HS;
    float* mgs = smf + SM_MG;
    float* b1s = smf + SM_B1;
    float* b2s = smf + SM_B2;
    // router scratch overlays hs (dead until first expert epilogue)
    float* rW1 = hs;            // 2048
    float* rb1 = hs + 2048;     // 16
    float* rW2 = hs + 2064;     // 128
    float* rb2 = hs + 2192;     // 8
    float* rfb = hs + 2208;     // 128*16 = 2048

    const int tid  = threadIdx.x;
    const int lane = tid & 31;
    const int wid  = tid >> 5;
    const int g    = lane >> 2;
    const int c    = lane & 3;
    const int mrow = (wid >> 1) * 32;
    const int ncol = (wid & 1) * 64;
    const long base = (long)blockIdx.x * TILE_M;

    // ---- load x tile (fp32, untruncated: router needs full precision) ----
#pragma unroll
    for (int i = 0; i < 16; i++) {
        int idx = tid + i * 256;
        int row = idx >> 5;
        int c4 = (idx & 31) << 2;
        float4 v = *reinterpret_cast<const float4*>(x + (base + row) * HDIM + c4);
        *reinterpret_cast<float4*>(xs + row * XS + c4) = v;
    }
    // ---- stage router weights + output biases ----
    for (int i = tid; i < 2048; i += 256) rW1[i] = Wr1[i];
    if (tid < 16)  rb1[tid] = br1[tid];
    if (tid < 128) rW2[tid] = Wr2[tid];
    if (tid < 8)   rb2[tid] = br2[tid];
    for (int i = tid; i < NRE * 128; i += 256) b2s[i] = be2[i];
    for (int i = tid; i < NSE * 128; i += 256) b2s[NRE * 128 + i] = bs2[i];
    __syncthreads();

    // ---- router stage 1: rf = relu(x @ Wr1 + br1), fp32, split 8 features/thread ----
    {
        int tok = tid & 127;
        int jb = (tid >> 7) * 8;
        float rf[8];
#pragma unroll
        for (int j = 0; j < 8; j++) rf[j] = rb1[jb + j];
        for (int h = 0; h < HDIM; h++) {
            float xv = xs[tok * XS + h];
#pragma unroll
            for (int j = 0; j < 8; j++) rf[j] += xv * rW1[h * 16 + jb + j];
        }
#pragma unroll
        for (int j = 0; j < 8; j++) rfb[tok * 16 + jb + j] = fmaxf(rf[j], 0.0f);
    }
    __syncthreads();
    // ---- router stage 2: logits -> softmax -> threshold mask -> renorm ----
    if (tid < 128) {
        float lg[8];
#pragma unroll
        for (int e = 0; e < 8; e++) lg[e] = rb2[e];
#pragma unroll
        for (int r = 0; r < 16; r++) {
            float v = rfb[tid * 16 + r];
#pragma unroll
            for (int e = 0; e < 8; e++) lg[e] += v * rW2[r * 8 + e];
        }
        float mx = lg[0];
#pragma unroll
        for (int e = 1; e < 8; e++) mx = fmaxf(mx, lg[e]);
        float s = 0.0f, gt[8];
#pragma unroll
        for (int e = 0; e < 8; e++) { gt[e] = expf(lg[e] - mx); s += gt[e]; }
        float inv = 1.0f / s;
        float msum = 0.0f;
#pragma unroll
        for (int e = 0; e < 8; e++) {
            float gv = gt[e] * inv;
            gv = (gv > 0.125f) ? gv : 0.0f;
            gt[e] = gv;
            msum += gv;
        }
        float innorm = 1.0f / (msum + 1e-8f);
#pragma unroll
        for (int e = 0; e < 8; e++) mgs[tid * 8 + e] = gt[e] * innorm;
    }
    __syncthreads();

    // ---- round x to tf32 in place (router done; expert GEMMs read pre-rounded) ----
    for (int i = tid; i < TILE_M * HDIM; i += 256) {
        int row = i >> 7, col = i & 127;
        float* p = xs + row * XS + col;
        *p = __uint_as_float(f2tf(*p));
    }

    float facc[2][8][4];
#pragma unroll
    for (int i = 0; i < 2; i++)
#pragma unroll
        for (int j = 0; j < 8; j++)
#pragma unroll
            for (int r = 0; r < 4; r++) facc[i][j][r] = 0.0f;

    // ---- expert loop: 8 routed + 2 shared ----
    for (int e = 0; e < NEXP; e++) {
        const float* W1 = (e < NRE) ? (We1 + e * HDIM * 128) : (Ws1 + (e - NRE) * HDIM * 128);
        const float* b1 = (e < NRE) ? (be1 + e * 128) : (bs1 + (e - NRE) * 128);
        const float* W2 = (e < NRE) ? (We2 + e * 128 * 128) : (Ws2 + (e - NRE) * 128 * 128);

        __syncthreads();                 // ws + hs free from previous iteration / prologue
        load_w_tf32(W1, wsm, tid);
        if (tid < 128) b1s[tid] = b1[tid];
        __syncthreads();

        // GEMM1: acc = x @ W1
        float acc[2][8][4];
#pragma unroll
        for (int i = 0; i < 2; i++)
#pragma unroll
            for (int j = 0; j < 8; j++)
#pragma unroll
                for (int r = 0; r < 4; r++) acc[i][j][r] = 0.0f;
        gemm128(xs, wsm, mrow, ncol, g, c, acc);

        // epilogue: h = mg * gelu(acc + b1), fold routing weight into h
#pragma unroll
        for (int i = 0; i < 2; i++)
#pragma unroll
            for (int j = 0; j < 8; j++)
#pragma unroll
                for (int rr = 0; rr < 2; rr++) {
                    int row = mrow + i * 16 + g + rr * 8;
                    int col = ncol + j * 8 + 2 * c;
                    float w = (e < NRE) ? mgs[row * 8 + e] : 1.0f;
                    float v0 = acc[i][j][rr * 2 + 0] + b1s[col];
                    float v1 = acc[i][j][rr * 2 + 1] + b1s[col + 1];
                    float2 hv;
                    hv.x = __uint_as_float(f2tf(w * gelu_tanh(v0)));
                    hv.y = __uint_as_float(f2tf(w * gelu_tanh(v1)));
                    *reinterpret_cast<float2*>(hs + row * XS + col) = hv;
                }
        __syncthreads();                 // all GEMM1 reads of ws done, hs fully written
        load_w_tf32(W2, wsm, tid);
        __syncthreads();

        // GEMM2: facc += h_scaled @ W2  (accumulates across all experts)
        gemm128(hs, wsm, mrow, ncol, g, c, facc);
    }

    // ---- writeout: + rank-10 bias correction (mg·be2 + sum bs2) ----
#pragma unroll
    for (int i = 0; i < 2; i++)
#pragma unroll
        for (int j = 0; j < 8; j++)
#pragma unroll
            for (int rr = 0; rr < 2; rr++) {
                int row = mrow + i * 16 + g + rr * 8;
                int col = ncol + j * 8 + 2 * c;
                float v0 = facc[i][j][rr * 2 + 0];
                float v1 = facc[i][j][rr * 2 + 1];
#pragma unroll
                for (int e = 0; e < NRE; e++) {
                    float w = mgs[row * 8 + e];
                    v0 += w * b2s[e * 128 + col];
                    v1 += w * b2s[e * 128 + col + 1];
                }
                v0 += b2s[8 * 128 + col] + b2s[9 * 128 + col];
                v1 += b2s[8 * 128 + col + 1] + b2s[9 * 128 + col + 1];
                float2 o = make_float2(v0, v1);
                *reinterpret_cast<float2*>(out + (base + row) * HDIM + col) = o;
            }
}

extern "C" void kernel_launch(void* const* d_in, const int* in_sizes, int n_in,
                              void* d_out, int out_size) {
    const float* x   = (const float*)d_in[0];
    const float* Wr1 = (const float*)d_in[1];
    const float* br1 = (const float*)d_in[2];
    const float* Wr2 = (const float*)d_in[3];
    const float* br2 = (const float*)d_in[4];
    const float* We1 = (const float*)d_in[5];
    const float* be1 = (const float*)d_in[6];
    const float* We2 = (const float*)d_in[7];
    const float* be2 = (const float*)d_in[8];
    const float* Ws1 = (const float*)d_in[9];
    const float* bs1 = (const float*)d_in[10];
    const float* Ws2 = (const float*)d_in[11];
    const float* bs2 = (const float*)d_in[12];
    float* out = (float*)d_out;

    int ntok = in_sizes[0] / HDIM;
    int grid = ntok / TILE_M;
    size_t smem = SM_FLOATS * sizeof(float);
    cudaFuncSetAttribute(moe_fused_kernel, cudaFuncAttributeMaxDynamicSharedMemorySize, (int)smem);
    moe_fused_kernel<<<grid, 256, smem>>>(x, Wr1, br1, Wr2, br2,
                                          We1, be1, We2, be2,
                                          Ws1, bs1, Ws2, bs2, out);
}

// round 5
// speedup vs baseline: 1.2158x; 1.2158x over previous
#include <cuda_runtime.h>
#include <cstdint>
#include <math.h>

#define NRE 8
#define NEXP 10
#define XS 132     // plain x/h smem row stride (floats)

// ---- dynamic smem byte offsets (main kernel) ----
#define XF_OFF   0          // 65536: x in A-frag layout [t8][k16][l32][4] tf32
#define HS_OFF   65536      // 67584: [128][132] fp32 x staging -> h (tf32) for GEMM2
#define WR_OFF   133120     // 2 x 32768 weight ring, B-frag chunks [k8][j16][l32][2]
#define MGS_OFF  198656     // 4096: routing weights [128][8]
#define B1S_OFF  202752     // 5120: all expert b1 [10][128]
#define B2S_OFF  207872     // 5120: all expert b2 [10][128]
#define SMEM_BYTES 212992

// Expert-interleaved B-frag images: expert e occupies floats [e*32768, (e+1)*32768):
//   [e*32768 .. +16384)          = W1_e  ([k16][j16][l32][2], half-K chunk = 32KB contiguous)
//   [e*32768+16384 .. +32768)    = W2_e
// Chunk c (32KB) at byte offset c*32768: c = 4e+{0,1,2,3} = {W1h0, W1h1, W2h0, W2h1} of expert e.
__device__ __align__(16) float g_wfrag[20 * 16384];

// ---------------- helpers ----------------
static __device__ __forceinline__ unsigned f2tf(float x) {
    unsigned u; asm("cvt.rna.tf32.f32 %0, %1;" : "=r"(u) : "f"(x)); return u;
}
static __device__ __forceinline__ float tf(float x) { return __uint_as_float(f2tf(x)); }
static __device__ __forceinline__ uint32_t s2u(const void* p) {
    uint32_t a;
    asm("{ .reg .u64 t; cvta.to.shared.u64 t, %1; cvt.u32.u64 %0, t; }" : "=r"(a) : "l"(p));
    return a;
}
static __device__ __forceinline__ void mma_tf32(float d[4], const unsigned a[4], const unsigned b[2]) {
    asm volatile(
        "mma.sync.aligned.m16n8k8.row.col.f32.tf32.tf32.f32 "
        "{%0,%1,%2,%3}, {%4,%5,%6,%7}, {%8,%9}, {%0,%1,%2,%3};"
        : "+f"(d[0]), "+f"(d[1]), "+f"(d[2]), "+f"(d[3])
        : "r"(a[0]), "r"(a[1]), "r"(a[2]), "r"(a[3]), "r"(b[0]), "r"(b[1]));
}
static __device__ __forceinline__ float gelu_tanh(float x) {
    float x3 = x * x * x;
    float inner = 0.7978845608028654f * (x + 0.044715f * x3);
    return 0.5f * x * (1.0f + tanhf(inner));
}
static __device__ __forceinline__ void cp16(uint32_t dst, const void* src) {
    asm volatile("cp.async.cg.shared.global [%0], [%1], 16;" :: "r"(dst), "l"(src) : "memory");
}
#define CP_COMMIT() asm volatile("cp.async.commit_group;" ::: "memory")
#define CP_WAIT1()  asm volatile("cp.async.wait_group 1;" ::: "memory")

// ============ prep: rewrite weights into B-frag order, tf32-rounded ============
__global__ void __launch_bounds__(256, 1)
prep_kernel(const float* __restrict__ We1, const float* __restrict__ Ws1,
            const float* __restrict__ We2, const float* __restrict__ Ws2) {
    extern __shared__ float ws[];          // [128][132]
    int m = blockIdx.x;                    // 0..7 We1, 8..9 Ws1, 10..17 We2, 18..19 Ws2
    const float* W;
    int ee, isw2;
    if (m < 8)       { W = We1 + m * 16384;        ee = m;      isw2 = 0; }
    else if (m < 10) { W = Ws1 + (m - 8) * 16384;  ee = m;      isw2 = 0; }
    else if (m < 18) { W = We2 + (m - 10) * 16384; ee = m - 10; isw2 = 1; }
    else             { W = Ws2 + (m - 18) * 16384; ee = m - 10; isw2 = 1; }
    const int tid = threadIdx.x;
#pragma unroll
    for (int it = 0; it < 16; it++) {
        int idx = it * 256 + tid;          // float4 index
        int row = idx >> 5, c4 = (idx & 31) << 2;
        float4 v = *reinterpret_cast<const float4*>(W + row * 128 + c4);
        v.x = tf(v.x); v.y = tf(v.y); v.z = tf(v.z); v.w = tf(v.w);
        *reinterpret_cast<float4*>(ws + row * XS + c4) = v;
    }
    __syncthreads();
    // expert-interleaved destination: W1_e at e*32768 floats, W2_e at e*32768+16384
    float* dst = g_wfrag + (size_t)ee * 32768 + (size_t)isw2 * 16384;
#pragma unroll
    for (int it = 0; it < 32; it++) {
        int i = it * 256 + tid;            // entry 0..8191: [k][j][l]
        int l = i & 31, j = (i >> 5) & 15, k = i >> 9;
        int g = l >> 2, c = l & 3;
        float2 o;
        o.x = ws[(8 * k + c) * XS + 8 * j + g];
        o.y = ws[(8 * k + c + 4) * XS + 8 * j + g];
        *reinterpret_cast<float2*>(dst + i * 2) = o;
    }
}

// ============ main fused kernel ============
__global__ void __launch_bounds__(256, 1)
moe_kernel(const float* __restrict__ x,
           const float* __restrict__ Wr1, const float* __restrict__ br1,
           const float* __restrict__ Wr2, const float* __restrict__ br2,
           const float* __restrict__ be1, const float* __restrict__ be2,
           const float* __restrict__ bs1, const float* __restrict__ bs2,
           float* __restrict__ out) {
    extern __shared__ char smem[];
    const uint32_t sb = s2u(smem);
    float4* xf = (float4*)(smem + XF_OFF);
    float*  hs = (float*)(smem + HS_OFF);
    float*  mgs = (float*)(smem + MGS_OFF);
    float*  b1s = (float*)(smem + B1S_OFF);
    float*  b2s = (float*)(smem + B2S_OFF);
    // router scratch overlays XF (packed only after router completes)
    float* rW1 = (float*)(smem + XF_OFF);
    float* rb1 = rW1 + 2048;
    float* rW2 = rW1 + 2064;
    float* rb2 = rW1 + 2192;
    float* rfb = rW1 + 2208;

    const int tid  = threadIdx.x;
    const int lane = tid & 31;
    const int wid  = tid >> 5;
    const int g    = lane >> 2;
    const int c    = lane & 3;
    const int t0   = (wid >> 1) * 2;       // first 16-row tile of this warp
    const int mrow = t0 * 16;
    const int jb   = (wid & 1) * 8;        // first n8 tile
    const int ncol = jb * 8;
    const long base = (long)blockIdx.x * 128;

    // ---- issue first two weight chunks immediately (overlaps everything below) ----
    {
        const char* src0 = (const char*)g_wfrag;
        uint32_t d0 = sb + WR_OFF, d1 = sb + WR_OFF + 32768u;
#pragma unroll
        for (int i = 0; i < 8; i++) { uint32_t o = (uint32_t)(tid + i * 256) * 16u; cp16(d0 + o, src0 + o); }
        CP_COMMIT();
#pragma unroll
        for (int i = 0; i < 8; i++) { uint32_t o = (uint32_t)(tid + i * 256) * 16u; cp16(d1 + o, src0 + 32768 + o); }
        CP_COMMIT();
    }

    // ---- stage x tile (fp32) + biases + router weights ----
#pragma unroll
    for (int it = 0; it < 16; it++) {
        int idx = it * 256 + tid;
        int row = idx >> 5, c4 = (idx & 31) << 2;
        float4 v = *reinterpret_cast<const float4*>(x + (base + row) * 128 + c4);
        *reinterpret_cast<float4*>(hs + row * XS + c4) = v;
    }
    for (int i = tid; i < 1280; i += 256) b1s[i] = (i < 1024) ? be1[i] : bs1[i - 1024];
    for (int i = tid; i < 1280; i += 256) b2s[i] = (i < 1024) ? be2[i] : bs2[i - 1024];
    for (int i = tid; i < 2048; i += 256) rW1[i] = Wr1[i];
    if (tid < 16)  rb1[tid] = br1[tid];
    if (tid < 128) rW2[tid] = Wr2[tid];
    if (tid < 8)   rb2[tid] = br2[tid];
    __syncthreads();

    // ---- router stage 1 (fp32) ----
    {
        int tok = tid & 127, jfb = (tid >> 7) * 8;
        float rf[8];
#pragma unroll
        for (int j = 0; j < 8; j++) rf[j] = rb1[jfb + j];
        for (int h = 0; h < 128; h++) {
            float xv = hs[tok * XS + h];
#pragma unroll
            for (int j = 0; j < 8; j++) rf[j] += xv * rW1[h * 16 + jfb + j];
        }
#pragma unroll
        for (int j = 0; j < 8; j++) rfb[tok * 16 + jfb + j] = fmaxf(rf[j], 0.0f);
    }
    __syncthreads();
    // ---- router stage 2: softmax -> threshold -> renorm ----
    if (tid < 128) {
        float lg[8];
#pragma unroll
        for (int e = 0; e < 8; e++) lg[e] = rb2[e];
#pragma unroll
        for (int r = 0; r < 16; r++) {
            float v = rfb[tid * 16 + r];
#pragma unroll
            for (int e = 0; e < 8; e++) lg[e] += v * rW2[r * 8 + e];
        }
        float mx = lg[0];
#pragma unroll
        for (int e = 1; e < 8; e++) mx = fmaxf(mx, lg[e]);
        float s = 0.0f, gt[8];
#pragma unroll
        for (int e = 0; e < 8; e++) { gt[e] = expf(lg[e] - mx); s += gt[e]; }
        float inv = 1.0f / s, msum = 0.0f;
#pragma unroll
        for (int e = 0; e < 8; e++) {
            float gv = gt[e] * inv;
            gv = (gv > 0.125f) ? gv : 0.0f;
            gt[e] = gv; msum += gv;
        }
        float innorm = 1.0f / (msum + 1e-8f);
#pragma unroll
        for (int e = 0; e < 8; e++) mgs[tid * 8 + e] = gt[e] * innorm;
    }
    __syncthreads();            // router scratch in XF now dead

    // ---- pack x -> XF A-frag layout [t][k][l][4], tf32 ----
#pragma unroll
    for (int it = 0; it < 16; it++) {
        int i = it * 256 + tid;            // = (t*16+k)*32 + l
        int l = i & 31, k = (i >> 5) & 15, t = i >> 9;
        int gg = l >> 2, cc = l & 3;
        const float* p0 = hs + (16 * t + gg) * XS + 8 * k + cc;
        float4 v;
        v.x = tf(p0[0]);
        v.y = tf(p0[8 * XS]);
        v.z = tf(p0[4]);
        v.w = tf(p0[8 * XS + 4]);
        xf[i] = v;
    }
    __syncthreads();

    float facc[2][8][4];
#pragma unroll
    for (int i = 0; i < 2; i++)
#pragma unroll
        for (int j = 0; j < 8; j++)
#pragma unroll
            for (int r = 0; r < 4; r++) facc[i][j][r] = 0.0f;

    const float2* wr0 = (const float2*)(smem + WR_OFF);
    const float2* wr1 = (const float2*)(smem + WR_OFF + 32768);

    // ---- expert loop ----
    for (int e = 0; e < NEXP; e++) {
        float acc[2][8][4];
#pragma unroll
        for (int i = 0; i < 2; i++)
#pragma unroll
            for (int j = 0; j < 8; j++)
#pragma unroll
                for (int r = 0; r < 4; r++) acc[i][j][r] = 0.0f;

        // ===== GEMM1 half 0 (ksteps 0..7), weights in buf0 =====
        CP_WAIT1(); __syncthreads();
#pragma unroll
        for (int k = 0; k < 8; k++) {
            unsigned a[2][4];
#pragma unroll
            for (int i = 0; i < 2; i++) {
                float4 av = xf[((t0 + i) * 16 + k) * 32 + lane];
                a[i][0] = __float_as_uint(av.x); a[i][1] = __float_as_uint(av.y);
                a[i][2] = __float_as_uint(av.z); a[i][3] = __float_as_uint(av.w);
            }
#pragma unroll
            for (int j = 0; j < 8; j++) {
                float2 bv = wr0[(k * 16 + jb + j) * 32 + lane];
                unsigned b[2] = { __float_as_uint(bv.x), __float_as_uint(bv.y) };
                mma_tf32(acc[0][j], a[0], b);
                mma_tf32(acc[1][j], a[1], b);
            }
        }
        __syncthreads();
        {   // issue chunk 4e+2 (W2_e half0) -> buf0
            const char* src = (const char*)g_wfrag + (size_t)(4 * e + 2) * 32768;
            uint32_t d = sb + WR_OFF;
#pragma unroll
            for (int i = 0; i < 8; i++) { uint32_t o = (uint32_t)(tid + i * 256) * 16u; cp16(d + o, src + o); }
            CP_COMMIT();
        }

        // ===== GEMM1 half 1 (ksteps 8..15), weights in buf1 =====
        CP_WAIT1(); __syncthreads();
#pragma unroll
        for (int k = 0; k < 8; k++) {
            unsigned a[2][4];
#pragma unroll
            for (int i = 0; i < 2; i++) {
                float4 av = xf[((t0 + i) * 16 + 8 + k) * 32 + lane];
                a[i][0] = __float_as_uint(av.x); a[i][1] = __float_as_uint(av.y);
                a[i][2] = __float_as_uint(av.z); a[i][3] = __float_as_uint(av.w);
            }
#pragma unroll
            for (int j = 0; j < 8; j++) {
                float2 bv = wr1[(k * 16 + jb + j) * 32 + lane];
                unsigned b[2] = { __float_as_uint(bv.x), __float_as_uint(bv.y) };
                mma_tf32(acc[0][j], a[0], b);
                mma_tf32(acc[1][j], a[1], b);
            }
        }
        // ===== epilogue: h = tf32(mg * gelu(acc + b1)) -> HS =====
        const float* b1 = b1s + e * 128;
#pragma unroll
        for (int i = 0; i < 2; i++)
#pragma unroll
            for (int j = 0; j < 8; j++)
#pragma unroll
                for (int rr = 0; rr < 2; rr++) {
                    int row = mrow + i * 16 + g + rr * 8;
                    int col = ncol + j * 8 + 2 * c;
                    float w = (e < NRE) ? mgs[row * 8 + e] : 1.0f;
                    float v0 = acc[i][j][rr * 2 + 0] + b1[col];
                    float v1 = acc[i][j][rr * 2 + 1] + b1[col + 1];
                    float2 hv;
                    hv.x = tf(w * gelu_tanh(v0));
                    hv.y = tf(w * gelu_tanh(v1));
                    *reinterpret_cast<float2*>(hs + row * XS + col) = hv;
                }
        __syncthreads();
        {   // issue chunk 4e+3 (W2_e half1) -> buf1
            const char* src = (const char*)g_wfrag + (size_t)(4 * e + 3) * 32768;
            uint32_t d = sb + WR_OFF + 32768u;
#pragma unroll
            for (int i = 0; i < 8; i++) { uint32_t o = (uint32_t)(tid + i * 256) * 16u; cp16(d + o, src + o); }
            CP_COMMIT();
        }

        // ===== GEMM2 half 0 (ksteps 0..7), A = hs plain, weights buf0 =====
        CP_WAIT1(); __syncthreads();
#pragma unroll
        for (int k = 0; k < 8; k++) {
            const int kb = k * 8;
            unsigned a[2][4];
#pragma unroll
            for (int i = 0; i < 2; i++) {
                const float* ap = hs + (mrow + i * 16 + g) * XS + kb + c;
                a[i][0] = __float_as_uint(ap[0]);
                a[i][1] = __float_as_uint(ap[8 * XS]);
                a[i][2] = __float_as_uint(ap[4]);
                a[i][3] = __float_as_uint(ap[8 * XS + 4]);
            }
#pragma unroll
            for (int j = 0; j < 8; j++) {
                float2 bv = wr0[(k * 16 + jb + j) * 32 + lane];
                unsigned b[2] = { __float_as_uint(bv.x), __float_as_uint(bv.y) };
                mma_tf32(facc[0][j], a[0], b);
                mma_tf32(facc[1][j], a[1], b);
            }
        }
        __syncthreads();
        if (e < 9) {   // issue chunk 4e+4 (next W1 half0) -> buf0
            const char* src = (const char*)g_wfrag + (size_t)(4 * e + 4) * 32768;
            uint32_t d = sb + WR_OFF;
#pragma unroll
            for (int i = 0; i < 8; i++) { uint32_t o = (uint32_t)(tid + i * 256) * 16u; cp16(d + o, src + o); }
            CP_COMMIT();
        }

        // ===== GEMM2 half 1 (ksteps 8..15), weights buf1 =====
        CP_WAIT1(); __syncthreads();
#pragma unroll
        for (int k = 0; k < 8; k++) {
            const int kb = 64 + k * 8;
            unsigned a[2][4];
#pragma unroll
            for (int i = 0; i < 2; i++) {
                const float* ap = hs + (mrow + i * 16 + g) * XS + kb + c;
                a[i][0] = __float_as_uint(ap[0]);
                a[i][1] = __float_as_uint(ap[8 * XS]);
                a[i][2] = __float_as_uint(ap[4]);
                a[i][3] = __float_as_uint(ap[8 * XS + 4]);
            }
#pragma unroll
            for (int j = 0; j < 8; j++) {
                float2 bv = wr1[(k * 16 + jb + j) * 32 + lane];
                unsigned b[2] = { __float_as_uint(bv.x), __float_as_uint(bv.y) };
                mma_tf32(facc[0][j], a[0], b);
                mma_tf32(facc[1][j], a[1], b);
            }
        }
        __syncthreads();
        if (e < 9) {   // issue chunk 4e+5 (next W1 half1) -> buf1
            const char* src = (const char*)g_wfrag + (size_t)(4 * e + 5) * 32768;
            uint32_t d = sb + WR_OFF + 32768u;
#pragma unroll
            for (int i = 0; i < 8; i++) { uint32_t o = (uint32_t)(tid + i * 256) * 16u; cp16(d + o, src + o); }
            CP_COMMIT();
        }
    }

    // ---- writeout: facc + rank-10 bias correction ----
#pragma unroll
    for (int i = 0; i < 2; i++)
#pragma unroll
        for (int j = 0; j < 8; j++)
#pragma unroll
            for (int rr = 0; rr < 2; rr++) {
                int row = mrow + i * 16 + g + rr * 8;
                int col = ncol + j * 8 + 2 * c;
                float v0 = facc[i][j][rr * 2 + 0];
                float v1 = facc[i][j][rr * 2 + 1];
#pragma unroll
                for (int e = 0; e < NRE; e++) {
                    float w = mgs[row * 8 + e];
                    v0 += w * b2s[e * 128 + col];
                    v1 += w * b2s[e * 128 + col + 1];
                }
                v0 += b2s[8 * 128 + col] + b2s[9 * 128 + col];
                v1 += b2s[8 * 128 + col + 1] + b2s[9 * 128 + col + 1];
                *reinterpret_cast<float2*>(out + (base + row) * 128 + col) = make_float2(v0, v1);
            }
}

extern "C" void kernel_launch(void* const* d_in, const int* in_sizes, int n_in,
                              void* d_out, int out_size) {
    const float* x   = (const float*)d_in[0];
    const float* Wr1 = (const float*)d_in[1];
    const float* br1 = (const float*)d_in[2];
    const float* Wr2 = (const float*)d_in[3];
    const float* br2 = (const float*)d_in[4];
    const float* We1 = (const float*)d_in[5];
    const float* be1 = (const float*)d_in[6];
    const float* We2 = (const float*)d_in[7];
    const float* be2 = (const float*)d_in[8];
    const float* Ws1 = (const float*)d_in[9];
    const float* bs1 = (const float*)d_in[10];
    const float* Ws2 = (const float*)d_in[11];
    const float* bs2 = (const float*)d_in[12];
    float* out = (float*)d_out;

    size_t prep_smem = 128 * XS * sizeof(float);
    cudaFuncSetAttribute(prep_kernel, cudaFuncAttributeMaxDynamicSharedMemorySize, (int)prep_smem);
    prep_kernel<<<20, 256, prep_smem>>>(We1, Ws1, We2, Ws2);

    int ntok = in_sizes[0] / 128;
    int grid = ntok / 128;
    cudaFuncSetAttribute(moe_kernel, cudaFuncAttributeMaxDynamicSharedMemorySize, SMEM_BYTES);
    moe_kernel<<<grid, 256, SMEM_BYTES>>>(x, Wr1, br1, Wr2, br2,
                                          be1, be2, bs1, bs2, out);
}